// round 8
// baseline (speedup 1.0000x reference)
#include <cuda_runtime.h>
#include <cuda_bf16.h>
#include <stdint.h>

// GRU persistent scan, warp-level bf16 MMA (m16n8k16), sm_103-safe ISA.
// R8: pre-split x/h to bf16 hi/lo (no in-loop cvt), 8 warps/CTA with K-split
// (2 warps per SMSP for latency hiding). 128 CTAs x 256 threads, single wave.

#define TT 1024
#define II 256
#define HHID 512
#define NB 128
#define GRID 128
#define NTHREADS 256
#define WSTRIDE 776
#define WLO   (48 * WSTRIDE * 2)          // bytes: lo component offset
#define WBYTES (48 * WSTRIDE * 2 * 2)
#define NSCR  (48 * 33)
#define SMEM_BYTES (WBYTES + (3 * NSCR + 64) * 4)

__device__ __nv_bfloat16 g_xhi[(size_t)NB * TT * II];
__device__ __nv_bfloat16 g_xlo[(size_t)NB * TT * II];
__device__ __nv_bfloat16 g_hhi[2][NB * HHID];
__device__ __nv_bfloat16 g_hlo[2][NB * HHID];
__device__ int g_count;
__device__ volatile int g_flag;

__device__ __forceinline__ uint32_t smem_u32(const void* p) {
    uint32_t a;
    asm("{ .reg .u64 t; cvta.to.shared.u64 t, %1; cvt.u32.u64 %0, t; }"
        : "=r"(a) : "l"(p));
    return a;
}
__device__ __forceinline__ void ldsm4(uint32_t a, unsigned& r0, unsigned& r1,
                                      unsigned& r2, unsigned& r3) {
    asm volatile("ldmatrix.sync.aligned.m8n8.x4.shared.b16 {%0,%1,%2,%3}, [%4];"
                 : "=r"(r0), "=r"(r1), "=r"(r2), "=r"(r3) : "r"(a));
}
__device__ __forceinline__ void ldsm2(uint32_t a, unsigned& r0, unsigned& r1) {
    asm volatile("ldmatrix.sync.aligned.m8n8.x2.shared.b16 {%0,%1}, [%2];"
                 : "=r"(r0), "=r"(r1) : "r"(a));
}
__device__ __forceinline__ void mma_bf16(float* d, const unsigned* a,
                                         unsigned b0, unsigned b1) {
    asm volatile("mma.sync.aligned.m16n8k16.row.col.f32.bf16.bf16.f32 "
                 "{%0,%1,%2,%3}, {%4,%5,%6,%7}, {%8,%9}, {%0,%1,%2,%3};"
                 : "+f"(d[0]), "+f"(d[1]), "+f"(d[2]), "+f"(d[3])
                 : "r"(a[0]), "r"(a[1]), "r"(a[2]), "r"(a[3]), "r"(b0), "r"(b1));
}

// ---------------- prep: fp32 -> bf16 hi/lo (x once; h0 into buffer 1) ------
__global__ void prep_kernel(const float* __restrict__ x,
                            const float* __restrict__ h0) {
    size_t stride = (size_t)gridDim.x * blockDim.x;
    size_t base   = (size_t)blockIdx.x * blockDim.x + threadIdx.x;
    for (size_t i = base; i < (size_t)NB * TT * II; i += stride) {
        float v = x[i];
        __nv_bfloat16 h = __float2bfloat16(v);
        g_xhi[i] = h;
        g_xlo[i] = __float2bfloat16(v - __bfloat162float(h));
    }
    for (size_t j = base; j < (size_t)NB * HHID; j += stride) {
        float v = h0[j];
        __nv_bfloat16 h = __float2bfloat16(v);
        g_hhi[1][j] = h;
        g_hlo[1][j] = __float2bfloat16(v - __bfloat162float(h));
    }
}

__global__ void __launch_bounds__(NTHREADS, 1) gru_mma(
    const float* __restrict__ h0,
    const float* __restrict__ Wih, const float* __restrict__ bih,
    const float* __restrict__ Whh, const float* __restrict__ bhh,
    float* __restrict__ out)
{
    extern __shared__ char smc[];
    const int tid  = threadIdx.x;
    const int lane = tid & 31;
    const int w    = tid >> 5;
    const int bm0  = (blockIdx.x & 3) * 32;
    const int j0   = (blockIdx.x >> 2) * 16;
    const int wm   = (w & 1) * 16;           // warp m tile
    const int wn   = ((w >> 1) & 1) * 24;    // warp n tile
    const int ks   = w >> 2;                 // K half (0/1)

    __nv_bfloat16* Whi_s = (__nv_bfloat16*)smc;
    __nv_bfloat16* Wlo_s = (__nv_bfloat16*)(smc + WLO);
    for (int idx = tid; idx < 48 * 768; idx += NTHREADS) {
        int n = idx / 768, k = idx - n * 768;
        int g = (n >> 4) * HHID + j0 + (n & 15);
        float v = (k < II) ? Wih[g * II + k] : Whh[g * HHID + (k - II)];
        __nv_bfloat16 hi = __float2bfloat16(v);
        Whi_s[n * WSTRIDE + k] = hi;
        Wlo_s[n * WSTRIDE + k] = __float2bfloat16(v - __bfloat162float(hi));
    }
    float* scrX  = (float*)(smc + WBYTES);
    float* scrH0 = scrX + NSCR;
    float* scrH1 = scrX + 2 * NSCR;
    float* bias  = scrX + 3 * NSCR;
    if (tid < 16) {
        int j = j0 + tid;
        bias[tid]      = bih[j]            + bhh[j];
        bias[16 + tid] = bih[HHID + j]     + bhh[HHID + j];
        bias[32 + tid] = bih[2 * HHID + j];
        bias[48 + tid] = bhh[2 * HHID + j];
    }
    __syncthreads();

    // ldmatrix B-frag bases (row n, col-major k within step)
    const uint32_t sW = smem_u32(smc);
    const int q  = lane & 7;
    const int mi = lane >> 3;
    const uint32_t a4base = sW + (uint32_t)(((wn + 8 * (mi >> 1) + q) * WSTRIDE
                                             + 8 * (mi & 1)) * 2);
    const uint32_t a2base = sW + (uint32_t)(((wn + 16 + q) * WSTRIDE
                                             + 8 * (mi & 1)) * 2);

    // A-frag global bases (bf16 hi/lo, pre-packed pairs)
    const int rl = lane >> 2;
    const int c2 = (lane & 3) * 2;
    const __nv_bfloat16* pxh = g_xhi + (size_t)(bm0 + wm + rl) * TT * II + c2;
    const __nv_bfloat16* pxl = g_xlo + (size_t)(bm0 + wm + rl) * TT * II + c2;
    const size_t XR8 = (size_t)8 * TT * II;

    // gate-thread state: 2 rows each
    const int mg  = (tid >> 4) * 2;
    const int jlg = tid & 15;
    float hprev[2];
    hprev[0] = h0[(bm0 + mg) * HHID + j0 + jlg];
    hprev[1] = h0[(bm0 + mg + 1) * HHID + j0 + jlg];

    unsigned buf[2][8][8];

#define LDX(CB, T_, CHK) {                                                    \
    _Pragma("unroll")                                                         \
    for (int s = 0; s < 8; s++) {                                             \
        size_t o = (size_t)(T_) * II + ((CHK) * 8 + s) * 16;                  \
        buf[CB][s][0] = *(const unsigned*)(pxh + o);                          \
        buf[CB][s][1] = *(const unsigned*)(pxh + o + XR8);                    \
        buf[CB][s][2] = *(const unsigned*)(pxh + o + 8);                      \
        buf[CB][s][3] = *(const unsigned*)(pxh + o + XR8 + 8);                \
        buf[CB][s][4] = *(const unsigned*)(pxl + o);                          \
        buf[CB][s][5] = *(const unsigned*)(pxl + o + XR8);                    \
        buf[CB][s][6] = *(const unsigned*)(pxl + o + 8);                      \
        buf[CB][s][7] = *(const unsigned*)(pxl + o + XR8 + 8);                \
    } }
#define LDH(CB, SH0) {                                                        \
    _Pragma("unroll")                                                         \
    for (int s = 0; s < 8; s++) {                                             \
        int o = ((SH0) + s) * 16;                                             \
        buf[CB][s][0] = *(const unsigned*)(phh + o);                          \
        buf[CB][s][1] = *(const unsigned*)(phh + o + 8 * HHID);               \
        buf[CB][s][2] = *(const unsigned*)(phh + o + 8);                      \
        buf[CB][s][3] = *(const unsigned*)(phh + o + 8 * HHID + 8);           \
        buf[CB][s][4] = *(const unsigned*)(phl + o);                          \
        buf[CB][s][5] = *(const unsigned*)(phl + o + 8 * HHID);               \
        buf[CB][s][6] = *(const unsigned*)(phl + o + 8);                      \
        buf[CB][s][7] = *(const unsigned*)(phl + o + 8 * HHID + 8);           \
    } }
#define CMP(CB, KB0, ACC) {                                                   \
    _Pragma("unroll")                                                         \
    for (int s = 0; s < 8; s++) {                                             \
        uint32_t kb = (uint32_t)(((KB0) + s) * 32);                           \
        const unsigned* ah = &buf[CB][s][0];                                  \
        const unsigned* al = &buf[CB][s][4];                                  \
        unsigned h0r, h1r, h2r, h3r, h4r, h5r;                                \
        unsigned l0r, l1r, l2r, l3r, l4r, l5r;                                \
        ldsm4(a4base + kb, h0r, h1r, h2r, h3r);                               \
        ldsm2(a2base + kb, h4r, h5r);                                         \
        ldsm4(a4base + WLO + kb, l0r, l1r, l2r, l3r);                         \
        ldsm2(a2base + WLO + kb, l4r, l5r);                                   \
        mma_bf16(ACC[0], ah, h0r, h1r);                                       \
        mma_bf16(ACC[1], ah, h2r, h3r);                                       \
        mma_bf16(ACC[2], ah, h4r, h5r);                                       \
        mma_bf16(ACC[0], ah, l0r, l1r);                                       \
        mma_bf16(ACC[1], ah, l2r, l3r);                                       \
        mma_bf16(ACC[2], ah, l4r, l5r);                                       \
        mma_bf16(ACC[0], al, h0r, h1r);                                       \
        mma_bf16(ACC[1], al, h2r, h3r);                                       \
        mma_bf16(ACC[2], al, h4r, h5r);                                       \
    } }
#define STORE_FRAGS(ACC, SCR) {                                               \
    _Pragma("unroll")                                                         \
    for (int nf = 0; nf < 3; nf++) {                                          \
        int n0 = wn + nf * 8 + (lane & 3) * 2;                                \
        int r0 = wm + (lane >> 2);                                            \
        (SCR)[n0 * 33 + r0]           = ACC[nf][0];                           \
        (SCR)[(n0 + 1) * 33 + r0]     = ACC[nf][1];                           \
        (SCR)[n0 * 33 + r0 + 8]       = ACC[nf][2];                           \
        (SCR)[(n0 + 1) * 33 + r0 + 8] = ACC[nf][3];                           \
    } }

    if (ks == 0) LDX(0, 0, 0);   // prefetch first x chunk

    for (int t = 0; t < TT; t++) {
        const int pr = (t + 1) & 1;
        const int pw = t & 1;
        const __nv_bfloat16* phh = g_hhi[pr] + (bm0 + wm + rl) * HHID + c2;
        const __nv_bfloat16* phl = g_hlo[pr] + (bm0 + wm + rl) * HHID + c2;

        if (ks == 0) {
            // K half 0: x k-steps 0..15, h k-steps 0..7 (global 0..23)
            float accX[3][4] = {{0,0,0,0},{0,0,0,0},{0,0,0,0}};
            float accH[3][4] = {{0,0,0,0},{0,0,0,0},{0,0,0,0}};
            LDX(1, t, 1);  CMP(0, 0, accX);
            LDH(0, 0);     CMP(1, 8, accX);
                           CMP(0, 16, accH);
            if (t + 1 < TT) LDX(0, t + 1, 0);
            STORE_FRAGS(accX, scrX);
            STORE_FRAGS(accH, scrH0);
        } else {
            // K half 1: h k-steps 8..31 (global 24..47)
            float accH[3][4] = {{0,0,0,0},{0,0,0,0},{0,0,0,0}};
            LDH(0, 8);
            LDH(1, 16);    CMP(0, 24, accH);
            LDH(0, 24);    CMP(1, 32, accH);
                           CMP(0, 40, accH);
            STORE_FRAGS(accH, scrH1);
        }
        __syncthreads();

        // ---- gates: thread owns (b = bm0+mg+i, j = j0+jlg), i in {0,1} ----
        #pragma unroll
        for (int i = 0; i < 2; i++) {
            int m = mg + i;
            float xr = scrX[jlg * 33 + m];
            float xz = scrX[(16 + jlg) * 33 + m];
            float xn = scrX[(32 + jlg) * 33 + m];
            float hr = scrH0[jlg * 33 + m]        + scrH1[jlg * 33 + m];
            float hz = scrH0[(16 + jlg) * 33 + m] + scrH1[(16 + jlg) * 33 + m];
            float hh = scrH0[(32 + jlg) * 33 + m] + scrH1[(32 + jlg) * 33 + m];
            float r  = 1.f / (1.f + __expf(-(xr + hr + bias[jlg])));
            float z  = 1.f / (1.f + __expf(-(xz + hz + bias[16 + jlg])));
            float n  = tanhf(xn + bias[32 + jlg] + r * (hh + bias[48 + jlg]));
            float hn = (1.f - z) * n + z * hprev[i];
            hprev[i] = hn;
            __nv_bfloat16 hb = __float2bfloat16(hn);
            int he = (bm0 + m) * HHID + j0 + jlg;
            g_hhi[pw][he] = hb;
            g_hlo[pw][he] = __float2bfloat16(hn - __bfloat162float(hb));
            if (t == TT - 1) {
                int o = (bm0 + m) * 2048 + j0 + jlg;
                out[o]                 = r;  out[o + 262144]        = r;
                out[o + 512]           = z;  out[o + 512 + 262144]  = z;
                out[o + 1024]          = n;  out[o + 1024 + 262144] = n;
                out[o + 1536]          = hn; out[o + 1536 + 262144] = hn;
            }
        }

        // ---- grid barrier (128 CTAs, single wave) ----
        if (t < TT - 1) {
            __threadfence();
            __syncthreads();
            if (tid == 0) {
                int old = atomicAdd(&g_count, 1);
                if (old == GRID - 1) {
                    g_count = 0;
                    __threadfence();
                    g_flag = t + 1;
                } else {
                    while (g_flag < t + 1) { }
                    __threadfence();
                }
            }
            __syncthreads();
        }
    }

    // reset barrier state for next graph replay
    __syncthreads();
    if (tid == 0) {
        int old = atomicAdd(&g_count, 1);
        if (old == GRID - 1) {
            g_count = 0;
            g_flag  = 0;
            __threadfence();
        }
    }
}

extern "C" void kernel_launch(void* const* d_in, const int* in_sizes, int n_in,
                              void* d_out, int out_size) {
    const float* x   = (const float*)d_in[0];
    const float* h   = (const float*)d_in[1];
    const float* Wih = (const float*)d_in[2];
    const float* bih = (const float*)d_in[3];
    const float* Whh = (const float*)d_in[4];
    const float* bhh = (const float*)d_in[5];
    float* out = (float*)d_out;

    prep_kernel<<<2048, 256>>>(x, h);

    cudaFuncSetAttribute(gru_mma, cudaFuncAttributeMaxDynamicSharedMemorySize,
                         SMEM_BYTES);
    gru_mma<<<GRID, NTHREADS, SMEM_BYTES>>>(h, Wih, bih, Whh, bhh, out);
}

// round 9
// speedup vs baseline: 1.4341x; 1.4341x over previous
#include <cuda_runtime.h>
#include <cuda_bf16.h>
#include <stdint.h>

// GRU persistent scan, warp bf16 MMA (m16n8k16), sm_103-safe ISA.
// R9: phase 1 computes x_proj for ALL t at full throughput (no barriers),
// phase 2 scan does h-GEMM only (K=512) -> much shorter latency-bound loop.
// 128 CTAs x 256 threads, single wave.

#define TT 1024
#define II 256
#define HHID 512
#define NB 128
#define GRID 128
#define NTHREADS 256
#define WSTRIDE 776
#define WLO   (48 * WSTRIDE * 2)
#define WBYTES (48 * WSTRIDE * 2 * 2)
#define NSCR  (48 * 33)
#define SMEM_BYTES (WBYTES + (2 * NSCR + 64) * 4)

__device__ __nv_bfloat16 g_xhi[(size_t)NB * TT * II];
__device__ __nv_bfloat16 g_xlo[(size_t)NB * TT * II];
__device__ __nv_bfloat16 g_hhi[2][NB * HHID];
__device__ __nv_bfloat16 g_hlo[2][NB * HHID];
__device__ float g_xp[(size_t)GRID * TT * 32 * 48];   // per-CTA x_proj slabs
__device__ int g_count;
__device__ volatile int g_flag;

__device__ __forceinline__ uint32_t smem_u32(const void* p) {
    uint32_t a;
    asm("{ .reg .u64 t; cvta.to.shared.u64 t, %1; cvt.u32.u64 %0, t; }"
        : "=r"(a) : "l"(p));
    return a;
}
__device__ __forceinline__ void ldsm4(uint32_t a, unsigned& r0, unsigned& r1,
                                      unsigned& r2, unsigned& r3) {
    asm volatile("ldmatrix.sync.aligned.m8n8.x4.shared.b16 {%0,%1,%2,%3}, [%4];"
                 : "=r"(r0), "=r"(r1), "=r"(r2), "=r"(r3) : "r"(a));
}
__device__ __forceinline__ void ldsm2(uint32_t a, unsigned& r0, unsigned& r1) {
    asm volatile("ldmatrix.sync.aligned.m8n8.x2.shared.b16 {%0,%1}, [%2];"
                 : "=r"(r0), "=r"(r1) : "r"(a));
}
__device__ __forceinline__ void mma_bf16(float* d, const unsigned* a,
                                         unsigned b0, unsigned b1) {
    asm volatile("mma.sync.aligned.m16n8k16.row.col.f32.bf16.bf16.f32 "
                 "{%0,%1,%2,%3}, {%4,%5,%6,%7}, {%8,%9}, {%0,%1,%2,%3};"
                 : "+f"(d[0]), "+f"(d[1]), "+f"(d[2]), "+f"(d[3])
                 : "r"(a[0]), "r"(a[1]), "r"(a[2]), "r"(a[3]), "r"(b0), "r"(b1));
}

// -------- prep: fp32 -> bf16 hi/lo (x once; h0 into ping-pong slot 1) -----
__global__ void prep_kernel(const float* __restrict__ x,
                            const float* __restrict__ h0) {
    size_t stride = (size_t)gridDim.x * blockDim.x;
    size_t base   = (size_t)blockIdx.x * blockDim.x + threadIdx.x;
    for (size_t i = base; i < (size_t)NB * TT * II; i += stride) {
        float v = x[i];
        __nv_bfloat16 h = __float2bfloat16(v);
        g_xhi[i] = h;
        g_xlo[i] = __float2bfloat16(v - __bfloat162float(h));
    }
    for (size_t j = base; j < (size_t)NB * HHID; j += stride) {
        float v = h0[j];
        __nv_bfloat16 h = __float2bfloat16(v);
        g_hhi[1][j] = h;
        g_hlo[1][j] = __float2bfloat16(v - __bfloat162float(h));
    }
}

__global__ void __launch_bounds__(NTHREADS, 1) gru_mma(
    const float* __restrict__ h0,
    const float* __restrict__ Wih, const float* __restrict__ bih,
    const float* __restrict__ Whh, const float* __restrict__ bhh,
    float* __restrict__ out)
{
    extern __shared__ char smc[];
    const int tid  = threadIdx.x;
    const int lane = tid & 31;
    const int w    = tid >> 5;
    const int bm0  = (blockIdx.x & 3) * 32;
    const int j0   = (blockIdx.x >> 2) * 16;
    const int wm   = (w & 1) * 16;           // warp m tile
    const int wn   = ((w >> 1) & 1) * 24;    // warp n tile
    const int kw   = w >> 2;                 // phase1: t parity; phase2: K half

    // ---- resident weights, bf16 hi/lo ----
    __nv_bfloat16* Whi_s = (__nv_bfloat16*)smc;
    __nv_bfloat16* Wlo_s = (__nv_bfloat16*)(smc + WLO);
    for (int idx = tid; idx < 48 * 768; idx += NTHREADS) {
        int n = idx / 768, k = idx - n * 768;
        int g = (n >> 4) * HHID + j0 + (n & 15);
        float v = (k < II) ? Wih[g * II + k] : Whh[g * HHID + (k - II)];
        __nv_bfloat16 hi = __float2bfloat16(v);
        Whi_s[n * WSTRIDE + k] = hi;
        Wlo_s[n * WSTRIDE + k] = __float2bfloat16(v - __bfloat162float(hi));
    }
    float* scrH0 = (float*)(smc + WBYTES);
    float* scrH1 = scrH0 + NSCR;
    float* bias  = scrH0 + 2 * NSCR;
    if (tid < 16) {
        int j = j0 + tid;
        bias[tid]      = bih[j]            + bhh[j];
        bias[16 + tid] = bih[HHID + j]     + bhh[HHID + j];
        bias[32 + tid] = bih[2 * HHID + j];
        bias[48 + tid] = bhh[2 * HHID + j];
    }
    __syncthreads();

    // ldmatrix B-frag bases
    const uint32_t sW = smem_u32(smc);
    const int q  = lane & 7;
    const int mi = lane >> 3;
    const uint32_t a4base = sW + (uint32_t)(((wn + 8 * (mi >> 1) + q) * WSTRIDE
                                             + 8 * (mi & 1)) * 2);
    const uint32_t a2base = sW + (uint32_t)(((wn + 16 + q) * WSTRIDE
                                             + 8 * (mi & 1)) * 2);

    // A-frag lane geometry
    const int rl = lane >> 2;
    const int c2 = (lane & 3) * 2;

    unsigned pbuf[2][4][8];
    float* xpc = g_xp + (size_t)blockIdx.x * TT * (32 * 48);

#define CMP4(PB, KBYTE0, ACC) {                                               \
    _Pragma("unroll")                                                         \
    for (int s = 0; s < 4; s++) {                                             \
        uint32_t kb = (uint32_t)((KBYTE0) + s * 32);                          \
        const unsigned* ah = &pbuf[PB][s][0];                                 \
        const unsigned* al = &pbuf[PB][s][4];                                 \
        unsigned h0r, h1r, h2r, h3r, h4r, h5r;                                \
        unsigned l0r, l1r, l2r, l3r, l4r, l5r;                                \
        ldsm4(a4base + kb, h0r, h1r, h2r, h3r);                               \
        ldsm2(a2base + kb, h4r, h5r);                                         \
        ldsm4(a4base + WLO + kb, l0r, l1r, l2r, l3r);                         \
        ldsm2(a2base + WLO + kb, l4r, l5r);                                   \
        mma_bf16(ACC[0], ah, h0r, h1r);                                       \
        mma_bf16(ACC[1], ah, h2r, h3r);                                       \
        mma_bf16(ACC[2], ah, h4r, h5r);                                       \
        mma_bf16(ACC[0], ah, l0r, l1r);                                       \
        mma_bf16(ACC[1], ah, l2r, l3r);                                       \
        mma_bf16(ACC[2], ah, l4r, l5r);                                       \
        mma_bf16(ACC[0], al, h0r, h1r);                                       \
        mma_bf16(ACC[1], al, h2r, h3r);                                       \
        mma_bf16(ACC[2], al, h4r, h5r);                                       \
    } }

    // ================= PHASE 1: x_proj for all t (throughput) =============
    {
        const __nv_bfloat16* pxh = g_xhi + (size_t)(bm0 + wm + rl) * TT * II + c2;
        const __nv_bfloat16* pxl = g_xlo + (size_t)(bm0 + wm + rl) * TT * II + c2;
        const size_t XR8 = (size_t)8 * TT * II;

#define LDX4(PB, T_, S0) {                                                    \
    _Pragma("unroll")                                                         \
    for (int s = 0; s < 4; s++) {                                             \
        size_t o = (size_t)(T_) * II + ((S0) + s) * 16;                       \
        pbuf[PB][s][0] = *(const unsigned*)(pxh + o);                         \
        pbuf[PB][s][1] = *(const unsigned*)(pxh + o + XR8);                   \
        pbuf[PB][s][2] = *(const unsigned*)(pxh + o + 8);                     \
        pbuf[PB][s][3] = *(const unsigned*)(pxh + o + XR8 + 8);               \
        pbuf[PB][s][4] = *(const unsigned*)(pxl + o);                         \
        pbuf[PB][s][5] = *(const unsigned*)(pxl + o + XR8);                   \
        pbuf[PB][s][6] = *(const unsigned*)(pxl + o + 8);                     \
        pbuf[PB][s][7] = *(const unsigned*)(pxl + o + XR8 + 8);               \
    } }

        LDX4(0, kw, 0);
        for (int t = kw; t < TT; t += 2) {          // warps split by t parity
            float acc[3][4] = {{0,0,0,0},{0,0,0,0},{0,0,0,0}};
            LDX4(1, t, 4);   CMP4(0, 0,       acc);
            LDX4(0, t, 8);   CMP4(1, 4 * 32,  acc);
            LDX4(1, t, 12);  CMP4(0, 8 * 32,  acc);
            if (t + 2 < TT) LDX4(0, t + 2, 0);
            CMP4(1, 12 * 32, acc);
            float* xpt = xpc + (size_t)t * (32 * 48);
            #pragma unroll
            for (int nf = 0; nf < 3; nf++) {
                int n0 = wn + nf * 8 + (lane & 3) * 2;
                int r0 = wm + (lane >> 2);
                *(float2*)(xpt + r0 * 48 + n0)       = make_float2(acc[nf][0], acc[nf][1]);
                *(float2*)(xpt + (r0 + 8) * 48 + n0) = make_float2(acc[nf][2], acc[nf][3]);
            }
        }
    }
    __syncthreads();   // xp slab complete (same-CTA visibility)

    // ================= PHASE 2: latency-critical scan =====================
    const int mg  = (tid >> 4) * 2;
    const int jlg = tid & 15;
    float hprev[2];
    hprev[0] = h0[(bm0 + mg) * HHID + j0 + jlg];
    hprev[1] = h0[(bm0 + mg + 1) * HHID + j0 + jlg];

    const uint32_t HKB = (uint32_t)((II + kw * 256) * 2);  // W byte-k base
    const int HR8 = 8 * HHID;

#define LDH4(PB, S0) {                                                        \
    _Pragma("unroll")                                                         \
    for (int s = 0; s < 4; s++) {                                             \
        int o = ((S0) + s) * 16;                                              \
        pbuf[PB][s][0] = *(const unsigned*)(phh + o);                         \
        pbuf[PB][s][1] = *(const unsigned*)(phh + o + HR8);                   \
        pbuf[PB][s][2] = *(const unsigned*)(phh + o + 8);                     \
        pbuf[PB][s][3] = *(const unsigned*)(phh + o + HR8 + 8);               \
        pbuf[PB][s][4] = *(const unsigned*)(phl + o);                         \
        pbuf[PB][s][5] = *(const unsigned*)(phl + o + HR8);                   \
        pbuf[PB][s][6] = *(const unsigned*)(phl + o + 8);                     \
        pbuf[PB][s][7] = *(const unsigned*)(phl + o + HR8 + 8);               \
    } }

    for (int t = 0; t < TT; t++) {
        const int pr = (t + 1) & 1;
        const int pw = t & 1;
        const __nv_bfloat16* phh = g_hhi[pr] + (bm0 + wm + rl) * HHID + kw * 256 + c2;
        const __nv_bfloat16* phl = g_hlo[pr] + (bm0 + wm + rl) * HHID + kw * 256 + c2;

        // h-critical loads first
        float acc[3][4] = {{0,0,0,0},{0,0,0,0},{0,0,0,0}};
        LDH4(0, 0);
        LDH4(1, 4);

        // x_proj gate prefetch (h-independent; own slab)
        const float* xpt = xpc + (size_t)t * (32 * 48);
        float xg[2][3];
        #pragma unroll
        for (int i = 0; i < 2; i++) {
            xg[i][0] = xpt[(mg + i) * 48 + jlg];
            xg[i][1] = xpt[(mg + i) * 48 + 16 + jlg];
            xg[i][2] = xpt[(mg + i) * 48 + 32 + jlg];
        }

        CMP4(0, HKB,           acc);
        LDH4(0, 8);
        CMP4(1, HKB + 4 * 32,  acc);
        LDH4(1, 12);
        CMP4(0, HKB + 8 * 32,  acc);
        CMP4(1, HKB + 12 * 32, acc);

        {
            float* scr = kw ? scrH1 : scrH0;
            #pragma unroll
            for (int nf = 0; nf < 3; nf++) {
                int n0 = wn + nf * 8 + (lane & 3) * 2;
                int r0 = wm + (lane >> 2);
                scr[n0 * 33 + r0]           = acc[nf][0];
                scr[(n0 + 1) * 33 + r0]     = acc[nf][1];
                scr[n0 * 33 + r0 + 8]       = acc[nf][2];
                scr[(n0 + 1) * 33 + r0 + 8] = acc[nf][3];
            }
        }
        __syncthreads();

        // ---- gates: thread owns (b = bm0+mg+i, j = j0+jlg) ----
        #pragma unroll
        for (int i = 0; i < 2; i++) {
            int m = mg + i;
            float hr = scrH0[jlg * 33 + m]        + scrH1[jlg * 33 + m];
            float hz = scrH0[(16 + jlg) * 33 + m] + scrH1[(16 + jlg) * 33 + m];
            float hh = scrH0[(32 + jlg) * 33 + m] + scrH1[(32 + jlg) * 33 + m];
            float r  = 1.f / (1.f + __expf(-(xg[i][0] + hr + bias[jlg])));
            float z  = 1.f / (1.f + __expf(-(xg[i][1] + hz + bias[16 + jlg])));
            float n  = tanhf(xg[i][2] + bias[32 + jlg] + r * (hh + bias[48 + jlg]));
            float hn = (1.f - z) * n + z * hprev[i];
            hprev[i] = hn;
            __nv_bfloat16 hb = __float2bfloat16(hn);
            int he = (bm0 + m) * HHID + j0 + jlg;
            g_hhi[pw][he] = hb;
            g_hlo[pw][he] = __float2bfloat16(hn - __bfloat162float(hb));
            if (t == TT - 1) {
                int o = (bm0 + m) * 2048 + j0 + jlg;
                out[o]                 = r;  out[o + 262144]        = r;
                out[o + 512]           = z;  out[o + 512 + 262144]  = z;
                out[o + 1024]          = n;  out[o + 1024 + 262144] = n;
                out[o + 1536]          = hn; out[o + 1536 + 262144] = hn;
            }
        }

        // ---- grid barrier (128 CTAs, single wave) ----
        if (t < TT - 1) {
            __threadfence();
            __syncthreads();
            if (tid == 0) {
                int old = atomicAdd(&g_count, 1);
                if (old == GRID - 1) {
                    g_count = 0;
                    __threadfence();
                    g_flag = t + 1;
                } else {
                    while (g_flag < t + 1) { }
                    __threadfence();
                }
            }
            __syncthreads();
        }
    }

    // reset barrier state for next graph replay
    __syncthreads();
    if (tid == 0) {
        int old = atomicAdd(&g_count, 1);
        if (old == GRID - 1) {
            g_count = 0;
            g_flag  = 0;
            __threadfence();
        }
    }
}

extern "C" void kernel_launch(void* const* d_in, const int* in_sizes, int n_in,
                              void* d_out, int out_size) {
    const float* x   = (const float*)d_in[0];
    const float* h   = (const float*)d_in[1];
    const float* Wih = (const float*)d_in[2];
    const float* bih = (const float*)d_in[3];
    const float* Whh = (const float*)d_in[4];
    const float* bhh = (const float*)d_in[5];
    float* out = (float*)d_out;

    prep_kernel<<<2048, 256>>>(x, h);

    cudaFuncSetAttribute(gru_mma, cudaFuncAttributeMaxDynamicSharedMemorySize,
                         SMEM_BYTES);
    gru_mma<<<GRID, NTHREADS, SMEM_BYTES>>>(h, Wih, bih, Whh, bhh, out);
}

// round 10
// speedup vs baseline: 2.3267x; 1.6224x over previous
#include <cuda_runtime.h>
#include <cuda_bf16.h>
#include <stdint.h>

// GRU persistent scan, warp bf16 MMA (m16n8k16), sm_103-safe ISA.
// R10: kill L1tex wavefront amplification.
//  - x pre-packed into A-fragment layout (coalesced LDG.128 in phase 1)
//  - h staged through SMEM each step (coalesced LDG.128 + ldmatrix)
// 128 CTAs x 256 threads, single wave. Phase 1: x_proj all t. Phase 2: scan.

#define TT 1024
#define II 256
#define HHID 512
#define NB 128
#define GRID 128
#define NTHREADS 256
#define WSTRIDE 776
#define WLO    (48 * WSTRIDE * 2)
#define WBYTES (48 * WSTRIDE * 2 * 2)      // 148992
#define SH_HI  148992                      // staged h hi (32 x 520 halfs)
#define SH_LO  182272
#define HSTB   1040                        // bytes per staged h row
#define SCR0B  215552
#define SCR1B  221888
#define BIASB  228224
#define SMEM_BYTES 228480

__device__ unsigned g_xf[(size_t)8 * TT * 16 * 256];   // x A-frags hi/lo, 128MB
__device__ __nv_bfloat16 g_hhi[2][NB * HHID];
__device__ __nv_bfloat16 g_hlo[2][NB * HHID];
__device__ float g_xp[(size_t)GRID * TT * 32 * 48];
__device__ int g_count;
__device__ volatile int g_flag;

__device__ __forceinline__ uint32_t smem_u32(const void* p) {
    uint32_t a;
    asm("{ .reg .u64 t; cvta.to.shared.u64 t, %1; cvt.u32.u64 %0, t; }"
        : "=r"(a) : "l"(p));
    return a;
}
__device__ __forceinline__ void ldsm4(uint32_t a, unsigned& r0, unsigned& r1,
                                      unsigned& r2, unsigned& r3) {
    asm volatile("ldmatrix.sync.aligned.m8n8.x4.shared.b16 {%0,%1,%2,%3}, [%4];"
                 : "=r"(r0), "=r"(r1), "=r"(r2), "=r"(r3) : "r"(a));
}
__device__ __forceinline__ void ldsm2(uint32_t a, unsigned& r0, unsigned& r1) {
    asm volatile("ldmatrix.sync.aligned.m8n8.x2.shared.b16 {%0,%1}, [%2];"
                 : "=r"(r0), "=r"(r1) : "r"(a));
}
__device__ __forceinline__ void mma4(float* d, unsigned a0, unsigned a1,
                                     unsigned a2, unsigned a3,
                                     unsigned b0, unsigned b1) {
    asm volatile("mma.sync.aligned.m16n8k16.row.col.f32.bf16.bf16.f32 "
                 "{%0,%1,%2,%3}, {%4,%5,%6,%7}, {%8,%9}, {%0,%1,%2,%3};"
                 : "+f"(d[0]), "+f"(d[1]), "+f"(d[2]), "+f"(d[3])
                 : "r"(a0), "r"(a1), "r"(a2), "r"(a3), "r"(b0), "r"(b1));
}
__device__ __forceinline__ void cvt_hilo(float2 v, unsigned& hi, unsigned& lo) {
    __nv_bfloat162 h2 = __float22bfloat162_rn(v);
    float2 hf = __bfloat1622float2(h2);
    __nv_bfloat162 l2 = __float22bfloat162_rn(make_float2(v.x - hf.x, v.y - hf.y));
    hi = reinterpret_cast<unsigned&>(h2);
    lo = reinterpret_cast<unsigned&>(l2);
}

// ------- prep: x -> fragment layout (via SMEM transpose); h0 -> hi/lo -------
__global__ void __launch_bounds__(256) prep_kernel(
    const float* __restrict__ x, const float* __restrict__ h0) {
    __shared__ float xs[16 * 260];
    const int bx  = blockIdx.x;          // = mt*1024 + t
    const int tid = threadIdx.x;
    const int mt  = bx >> 10;
    const int t   = bx & 1023;

    if (bx < 256) {                       // h0 split (65536 = 256*256)
        int i = bx * 256 + tid;
        float v = h0[i];
        __nv_bfloat16 h = __float2bfloat16(v);
        g_hhi[1][i] = h;
        g_hlo[1][i] = __float2bfloat16(v - __bfloat162float(h));
    }

    #pragma unroll
    for (int it = 0; it < 16; it++)       // 16 rows x 256 cols, coalesced
        xs[it * 260 + tid] = x[(size_t)(mt * 16 + it) * TT * II + (size_t)t * II + tid];
    __syncthreads();

    const int w    = tid >> 5;
    const int lane = tid & 31;
    const int rl   = lane >> 2;
    const int c2   = (lane & 3) * 2;
    #pragma unroll
    for (int sub = 0; sub < 2; sub++) {
        int ks = w * 2 + sub;
        int cb = ks * 16 + c2;
        unsigned h0r, l0r, h1r, l1r, h2r, l2r, h3r, l3r;
        cvt_hilo(make_float2(xs[rl * 260 + cb],       xs[rl * 260 + cb + 1]),       h0r, l0r);
        cvt_hilo(make_float2(xs[(rl + 8) * 260 + cb], xs[(rl + 8) * 260 + cb + 1]), h1r, l1r);
        cvt_hilo(make_float2(xs[rl * 260 + cb + 8],   xs[rl * 260 + cb + 9]),       h2r, l2r);
        cvt_hilo(make_float2(xs[(rl + 8) * 260 + cb + 8], xs[(rl + 8) * 260 + cb + 9]), h3r, l3r);
        unsigned* dst = g_xf + (((size_t)mt * TT + t) * 16 + ks) * 256 + lane * 4;
        *(uint4*)dst         = make_uint4(h0r, h1r, h2r, h3r);
        *(uint4*)(dst + 128) = make_uint4(l0r, l1r, l2r, l3r);
    }
}

__global__ void __launch_bounds__(NTHREADS, 1) gru_mma(
    const float* __restrict__ h0,
    const float* __restrict__ Wih, const float* __restrict__ bih,
    const float* __restrict__ Whh, const float* __restrict__ bhh,
    float* __restrict__ out)
{
    extern __shared__ char smc[];
    const int tid  = threadIdx.x;
    const int lane = tid & 31;
    const int w    = tid >> 5;
    const int bm0  = (blockIdx.x & 3) * 32;
    const int j0   = (blockIdx.x >> 2) * 16;
    const int wm   = (w & 1) * 16;
    const int wn   = ((w >> 1) & 1) * 24;
    const int kw   = w >> 2;             // phase1: t parity; phase2: K half

    // ---- resident weights, bf16 hi/lo ----
    __nv_bfloat16* Whi_s = (__nv_bfloat16*)smc;
    __nv_bfloat16* Wlo_s = (__nv_bfloat16*)(smc + WLO);
    for (int idx = tid; idx < 48 * 768; idx += NTHREADS) {
        int n = idx / 768, k = idx - n * 768;
        int g = (n >> 4) * HHID + j0 + (n & 15);
        float v = (k < II) ? Wih[g * II + k] : Whh[g * HHID + (k - II)];
        __nv_bfloat16 hi = __float2bfloat16(v);
        Whi_s[n * WSTRIDE + k] = hi;
        Wlo_s[n * WSTRIDE + k] = __float2bfloat16(v - __bfloat162float(hi));
    }
    float* scrH0 = (float*)(smc + SCR0B);
    float* scrH1 = (float*)(smc + SCR1B);
    float* bias  = (float*)(smc + BIASB);
    if (tid < 16) {
        int j = j0 + tid;
        bias[tid]      = bih[j]            + bhh[j];
        bias[16 + tid] = bih[HHID + j]     + bhh[HHID + j];
        bias[32 + tid] = bih[2 * HHID + j];
        bias[48 + tid] = bhh[2 * HHID + j];
    }
    __syncthreads();

    const uint32_t sb = smem_u32(smc);
    // B-frag (weights) ldmatrix bases
    const int q  = lane & 7;
    const int mi = lane >> 3;
    const uint32_t a4base = sb + (uint32_t)(((wn + 8 * (mi >> 1) + q) * WSTRIDE
                                             + 8 * (mi & 1)) * 2);
    const uint32_t a2base = sb + (uint32_t)(((wn + 16 + q) * WSTRIDE
                                             + 8 * (mi & 1)) * 2);
    // A-frag (staged h) ldmatrix bases: row = lane&15, colbase = (lane>>4)*8
    const uint32_t aAhi = sb + SH_HI + (uint32_t)((wm + (lane & 15)) * HSTB
                                                  + (lane >> 4) * 16 + kw * 512);
    const uint32_t aAlo = aAhi + (SH_LO - SH_HI);

#define CMPK(AH, AL, KB, ACC) {                                               \
    unsigned h0r,h1r,h2r,h3r,h4r,h5r,l0r,l1r,l2r,l3r,l4r,l5r;                 \
    ldsm4(a4base + (KB), h0r, h1r, h2r, h3r);                                 \
    ldsm2(a2base + (KB), h4r, h5r);                                           \
    ldsm4(a4base + WLO + (KB), l0r, l1r, l2r, l3r);                           \
    ldsm2(a2base + WLO + (KB), l4r, l5r);                                     \
    mma4(ACC[0], (AH).x,(AH).y,(AH).z,(AH).w, h0r, h1r);                      \
    mma4(ACC[1], (AH).x,(AH).y,(AH).z,(AH).w, h2r, h3r);                      \
    mma4(ACC[2], (AH).x,(AH).y,(AH).z,(AH).w, h4r, h5r);                      \
    mma4(ACC[0], (AH).x,(AH).y,(AH).z,(AH).w, l0r, l1r);                      \
    mma4(ACC[1], (AH).x,(AH).y,(AH).z,(AH).w, l2r, l3r);                      \
    mma4(ACC[2], (AH).x,(AH).y,(AH).z,(AH).w, l4r, l5r);                      \
    mma4(ACC[0], (AL).x,(AL).y,(AL).z,(AL).w, h0r, h1r);                      \
    mma4(ACC[1], (AL).x,(AL).y,(AL).z,(AL).w, h2r, h3r);                      \
    mma4(ACC[2], (AL).x,(AL).y,(AL).z,(AL).w, h4r, h5r); }

    float* xpc = g_xp + (size_t)blockIdx.x * TT * (32 * 48);

    // ================= PHASE 1: x_proj for all t (throughput) =============
    {
        const int mt = (blockIdx.x & 3) * 2 + (w & 1);
        for (int t = kw; t < TT; t += 2) {
            const uint4* xb = (const uint4*)g_xf
                              + ((size_t)mt * TT + t) * (16 * 64) + lane;
            float acc[3][4] = {{0,0,0,0},{0,0,0,0},{0,0,0,0}};
            #pragma unroll
            for (int ks = 0; ks < 16; ks++) {
                uint4 AH = xb[ks * 64];
                uint4 AL = xb[ks * 64 + 32];
                CMPK(AH, AL, (uint32_t)(ks * 32), acc);
            }
            float* xpt = xpc + (size_t)t * (32 * 48);
            #pragma unroll
            for (int nf = 0; nf < 3; nf++) {
                int n0 = wn + nf * 8 + (lane & 3) * 2;
                int r0 = wm + (lane >> 2);
                *(float2*)(xpt + r0 * 48 + n0)       = make_float2(acc[nf][0], acc[nf][1]);
                *(float2*)(xpt + (r0 + 8) * 48 + n0) = make_float2(acc[nf][2], acc[nf][3]);
            }
        }
    }
    __syncthreads();

    // ================= PHASE 2: latency-critical scan =====================
    const int mg  = (tid >> 4) * 2;
    const int jlg = tid & 15;
    float hprev[2];
    hprev[0] = h0[(bm0 + mg) * HHID + j0 + jlg];
    hprev[1] = h0[(bm0 + mg + 1) * HHID + j0 + jlg];

    const uint32_t HKB = (uint32_t)((II + kw * 256) * 2);   // weight k byte base

    for (int t = 0; t < TT; t++) {
        const int pr = (t + 1) & 1;
        const int pw = t & 1;

        // -- cooperative coalesced h load (critical path head) --
        const uint4* srcH = (const uint4*)(g_hhi[pr]) + bm0 * 64;
        const uint4* srcL = (const uint4*)(g_hlo[pr]) + bm0 * 64;
        uint4 vh[8], vl[8];
        #pragma unroll
        for (int it = 0; it < 8; it++) {
            vh[it] = srcH[it * 256 + tid];
            vl[it] = srcL[it * 256 + tid];
        }
        // -- x_proj gate operands (independent, issue early) --
        const float* xpt = xpc + (size_t)t * (32 * 48);
        float xg[2][3];
        #pragma unroll
        for (int i = 0; i < 2; i++) {
            xg[i][0] = xpt[(mg + i) * 48 + jlg];
            xg[i][1] = xpt[(mg + i) * 48 + 16 + jlg];
            xg[i][2] = xpt[(mg + i) * 48 + 32 + jlg];
        }
        #pragma unroll
        for (int it = 0; it < 8; it++) {
            int cc = it * 256 + tid;
            int row = cc >> 6, ch = cc & 63;
            *(uint4*)(smc + SH_HI + row * HSTB + ch * 16) = vh[it];
            *(uint4*)(smc + SH_LO + row * HSTB + ch * 16) = vl[it];
        }
        __syncthreads();

        // -- h-GEMM: 16 k-steps, 2 acc sets to break chains --
        float accA[3][4] = {{0,0,0,0},{0,0,0,0},{0,0,0,0}};
        float accB[3][4] = {{0,0,0,0},{0,0,0,0},{0,0,0,0}};
        #pragma unroll
        for (int ks = 0; ks < 16; ks += 2) {
            {
                uint32_t ka = (uint32_t)(ks * 32);
                unsigned a0,a1,a2,a3, b0,b1,b2,b3;
                ldsm4(aAhi + ka, a0, a1, a2, a3);
                ldsm4(aAlo + ka, b0, b1, b2, b3);
                uint4 AH = make_uint4(a0, a1, a2, a3);
                uint4 AL = make_uint4(b0, b1, b2, b3);
                CMPK(AH, AL, HKB + ka, accA);
            }
            {
                uint32_t ka = (uint32_t)((ks + 1) * 32);
                unsigned a0,a1,a2,a3, b0,b1,b2,b3;
                ldsm4(aAhi + ka, a0, a1, a2, a3);
                ldsm4(aAlo + ka, b0, b1, b2, b3);
                uint4 AH = make_uint4(a0, a1, a2, a3);
                uint4 AL = make_uint4(b0, b1, b2, b3);
                CMPK(AH, AL, HKB + ka, accB);
            }
        }
        {
            float* scr = kw ? scrH1 : scrH0;
            #pragma unroll
            for (int nf = 0; nf < 3; nf++) {
                int n0 = wn + nf * 8 + (lane & 3) * 2;
                int r0 = wm + (lane >> 2);
                scr[n0 * 33 + r0]           = accA[nf][0] + accB[nf][0];
                scr[(n0 + 1) * 33 + r0]     = accA[nf][1] + accB[nf][1];
                scr[n0 * 33 + r0 + 8]       = accA[nf][2] + accB[nf][2];
                scr[(n0 + 1) * 33 + r0 + 8] = accA[nf][3] + accB[nf][3];
            }
        }
        __syncthreads();

        // -- gates --
        #pragma unroll
        for (int i = 0; i < 2; i++) {
            int m = mg + i;
            float hr = scrH0[jlg * 33 + m]        + scrH1[jlg * 33 + m];
            float hz = scrH0[(16 + jlg) * 33 + m] + scrH1[(16 + jlg) * 33 + m];
            float hh = scrH0[(32 + jlg) * 33 + m] + scrH1[(32 + jlg) * 33 + m];
            float r  = 1.f / (1.f + __expf(-(xg[i][0] + hr + bias[jlg])));
            float z  = 1.f / (1.f + __expf(-(xg[i][1] + hz + bias[16 + jlg])));
            float n  = tanhf(xg[i][2] + bias[32 + jlg] + r * (hh + bias[48 + jlg]));
            float hn = (1.f - z) * n + z * hprev[i];
            hprev[i] = hn;
            __nv_bfloat16 hb = __float2bfloat16(hn);
            int he = (bm0 + m) * HHID + j0 + jlg;
            g_hhi[pw][he] = hb;
            g_hlo[pw][he] = __float2bfloat16(hn - __bfloat162float(hb));
            if (t == TT - 1) {
                int o = (bm0 + m) * 2048 + j0 + jlg;
                out[o]                 = r;  out[o + 262144]        = r;
                out[o + 512]           = z;  out[o + 512 + 262144]  = z;
                out[o + 1024]          = n;  out[o + 1024 + 262144] = n;
                out[o + 1536]          = hn; out[o + 1536 + 262144] = hn;
            }
        }

        // -- grid barrier (128 CTAs, single wave) --
        if (t < TT - 1) {
            __threadfence();
            __syncthreads();
            if (tid == 0) {
                int old = atomicAdd(&g_count, 1);
                if (old == GRID - 1) {
                    g_count = 0;
                    __threadfence();
                    g_flag = t + 1;
                } else {
                    while (g_flag < t + 1) { }
                    __threadfence();
                }
            }
            __syncthreads();
        }
    }

    // reset barrier state for next graph replay
    __syncthreads();
    if (tid == 0) {
        int old = atomicAdd(&g_count, 1);
        if (old == GRID - 1) {
            g_count = 0;
            g_flag  = 0;
            __threadfence();
        }
    }
}

extern "C" void kernel_launch(void* const* d_in, const int* in_sizes, int n_in,
                              void* d_out, int out_size) {
    const float* x   = (const float*)d_in[0];
    const float* h   = (const float*)d_in[1];
    const float* Wih = (const float*)d_in[2];
    const float* bih = (const float*)d_in[3];
    const float* Whh = (const float*)d_in[4];
    const float* bhh = (const float*)d_in[5];
    float* out = (float*)d_out;

    prep_kernel<<<8192, 256>>>(x, h);

    cudaFuncSetAttribute(gru_mma, cudaFuncAttributeMaxDynamicSharedMemorySize,
                         SMEM_BYTES);
    gru_mma<<<GRID, NTHREADS, SMEM_BYTES>>>(h, Wih, bih, Whh, bhh, out);
}

// round 11
// speedup vs baseline: 2.5530x; 1.0973x over previous
#include <cuda_runtime.h>
#include <cuda_bf16.h>
#include <stdint.h>

// GRU persistent scan, warp bf16 MMA (m16n8k16), sm_103-safe ISA.
// R11: h passed between steps in MMA-fragment-native layout (coalesced
// LDG.128 direct to A-regs, no SMEM staging on the critical path), and the
// global barrier split into 4 independent 32-CTA batch-group barriers.
// 128 CTAs x 256 threads, single wave. Phase 1: x_proj all t. Phase 2: scan.

#define TT 1024
#define II 256
#define HHID 512
#define NB 128
#define GRID 128
#define NTHREADS 256
#define GROUPN 32
#define WSTRIDE 776
#define WLO    (48 * WSTRIDE * 2)
#define WBYTES (48 * WSTRIDE * 2 * 2)      // 148992
#define SCR0B  148992                      // h-GEMM partials, K half 0
#define SCR1B  155328                      // K half 1
#define SCRFB  161664                      // new-h scratch (16 x 33 fp32)
#define BIASB  163776
#define SMEM_BYTES 164032

__device__ unsigned g_xf[(size_t)8 * TT * 16 * 256];     // x A-frags hi/lo
__device__ float    g_xp[(size_t)GRID * TT * 32 * 48];   // x_proj slabs
__device__ uint4    g_hf[2][8 * 32 * 2 * 32];            // h A-frags hi/lo
__device__ int g_count4[4 * 32];
__device__ volatile int g_flag4[4 * 32];

__device__ __forceinline__ uint32_t smem_u32(const void* p) {
    uint32_t a;
    asm("{ .reg .u64 t; cvta.to.shared.u64 t, %1; cvt.u32.u64 %0, t; }"
        : "=r"(a) : "l"(p));
    return a;
}
__device__ __forceinline__ void ldsm4(uint32_t a, unsigned& r0, unsigned& r1,
                                      unsigned& r2, unsigned& r3) {
    asm volatile("ldmatrix.sync.aligned.m8n8.x4.shared.b16 {%0,%1,%2,%3}, [%4];"
                 : "=r"(r0), "=r"(r1), "=r"(r2), "=r"(r3) : "r"(a));
}
__device__ __forceinline__ void ldsm2(uint32_t a, unsigned& r0, unsigned& r1) {
    asm volatile("ldmatrix.sync.aligned.m8n8.x2.shared.b16 {%0,%1}, [%2];"
                 : "=r"(r0), "=r"(r1) : "r"(a));
}
__device__ __forceinline__ void mma4(float* d, unsigned a0, unsigned a1,
                                     unsigned a2, unsigned a3,
                                     unsigned b0, unsigned b1) {
    asm volatile("mma.sync.aligned.m16n8k16.row.col.f32.bf16.bf16.f32 "
                 "{%0,%1,%2,%3}, {%4,%5,%6,%7}, {%8,%9}, {%0,%1,%2,%3};"
                 : "+f"(d[0]), "+f"(d[1]), "+f"(d[2]), "+f"(d[3])
                 : "r"(a0), "r"(a1), "r"(a2), "r"(a3), "r"(b0), "r"(b1));
}
__device__ __forceinline__ void cvt_hilo(float2 v, unsigned& hi, unsigned& lo) {
    __nv_bfloat162 h2 = __float22bfloat162_rn(v);
    float2 hf = __bfloat1622float2(h2);
    __nv_bfloat162 l2 = __float22bfloat162_rn(make_float2(v.x - hf.x, v.y - hf.y));
    hi = reinterpret_cast<unsigned&>(h2);
    lo = reinterpret_cast<unsigned&>(l2);
}

// ------- prep: x -> fragment layout; h0 -> fragment layout (slot 1) -------
__global__ void __launch_bounds__(256) prep_kernel(
    const float* __restrict__ x, const float* __restrict__ h0) {
    __shared__ float xs[16 * 260];
    const int bx  = blockIdx.x;
    const int tid = threadIdx.x;
    const int w    = tid >> 5;
    const int lane = tid & 31;
    const int rl   = lane >> 2;
    const int c2   = (lane & 3) * 2;
    const int mt  = bx >> 10;
    const int t   = bx & 1023;

    if (bx < 32) {                        // h0 -> g_hf[1] (256 tiles, 8/block)
        int tile = bx * 8 + w;            // tile = mt*32 + kc
        int mth = tile >> 5, kc = tile & 31;
        const float* hb = h0 + (size_t)(mth * 16) * HHID + kc * 16;
        unsigned h0r,l0r,h1r,l1r,h2r,l2r,h3r,l3r;
        cvt_hilo(make_float2(hb[rl*HHID+c2],       hb[rl*HHID+c2+1]),       h0r,l0r);
        cvt_hilo(make_float2(hb[(rl+8)*HHID+c2],   hb[(rl+8)*HHID+c2+1]),   h1r,l1r);
        cvt_hilo(make_float2(hb[rl*HHID+c2+8],     hb[rl*HHID+c2+9]),       h2r,l2r);
        cvt_hilo(make_float2(hb[(rl+8)*HHID+c2+8], hb[(rl+8)*HHID+c2+9]),   h3r,l3r);
        g_hf[1][(size_t)tile * 64 + lane]      = make_uint4(h0r,h1r,h2r,h3r);
        g_hf[1][(size_t)tile * 64 + 32 + lane] = make_uint4(l0r,l1r,l2r,l3r);
    }

    #pragma unroll
    for (int it = 0; it < 16; it++)
        xs[it * 260 + tid] = x[(size_t)(mt * 16 + it) * TT * II + (size_t)t * II + tid];
    __syncthreads();

    #pragma unroll
    for (int sub = 0; sub < 2; sub++) {
        int ks = w * 2 + sub;
        int cb = ks * 16 + c2;
        unsigned h0r, l0r, h1r, l1r, h2r, l2r, h3r, l3r;
        cvt_hilo(make_float2(xs[rl * 260 + cb],           xs[rl * 260 + cb + 1]),       h0r, l0r);
        cvt_hilo(make_float2(xs[(rl + 8) * 260 + cb],     xs[(rl + 8) * 260 + cb + 1]), h1r, l1r);
        cvt_hilo(make_float2(xs[rl * 260 + cb + 8],       xs[rl * 260 + cb + 9]),       h2r, l2r);
        cvt_hilo(make_float2(xs[(rl + 8) * 260 + cb + 8], xs[(rl + 8) * 260 + cb + 9]), h3r, l3r);
        unsigned* dst = g_xf + (((size_t)mt * TT + t) * 16 + ks) * 256 + lane * 4;
        *(uint4*)dst         = make_uint4(h0r, h1r, h2r, h3r);
        *(uint4*)(dst + 128) = make_uint4(l0r, l1r, l2r, l3r);
    }
}

__global__ void __launch_bounds__(NTHREADS, 1) gru_mma(
    const float* __restrict__ h0,
    const float* __restrict__ Wih, const float* __restrict__ bih,
    const float* __restrict__ Whh, const float* __restrict__ bhh,
    float* __restrict__ out)
{
    extern __shared__ char smc[];
    const int tid  = threadIdx.x;
    const int lane = tid & 31;
    const int w    = tid >> 5;
    const int grp  = blockIdx.x & 3;
    const int bm0  = grp * 32;
    const int j0   = (blockIdx.x >> 2) * 16;
    const int kcP  = blockIdx.x >> 2;        // produced h k-chunk
    const int wm   = (w & 1) * 16;
    const int wn   = ((w >> 1) & 1) * 24;
    const int kw   = w >> 2;                 // phase1: t parity; phase2: K half

    // ---- resident weights, bf16 hi/lo ----
    __nv_bfloat16* Whi_s = (__nv_bfloat16*)smc;
    __nv_bfloat16* Wlo_s = (__nv_bfloat16*)(smc + WLO);
    for (int idx = tid; idx < 48 * 768; idx += NTHREADS) {
        int n = idx / 768, k = idx - n * 768;
        int g = (n >> 4) * HHID + j0 + (n & 15);
        float v = (k < II) ? Wih[g * II + k] : Whh[g * HHID + (k - II)];
        __nv_bfloat16 hi = __float2bfloat16(v);
        Whi_s[n * WSTRIDE + k] = hi;
        Wlo_s[n * WSTRIDE + k] = __float2bfloat16(v - __bfloat162float(hi));
    }
    float* scrH0 = (float*)(smc + SCR0B);
    float* scrH1 = (float*)(smc + SCR1B);
    float* scrF  = (float*)(smc + SCRFB);
    float* bias  = (float*)(smc + BIASB);
    if (tid < 16) {
        int j = j0 + tid;
        bias[tid]      = bih[j]            + bhh[j];
        bias[16 + tid] = bih[HHID + j]     + bhh[HHID + j];
        bias[32 + tid] = bih[2 * HHID + j];
        bias[48 + tid] = bhh[2 * HHID + j];
    }
    __syncthreads();

    const uint32_t sb = smem_u32(smc);
    const int q  = lane & 7;
    const int mi = lane >> 3;
    const uint32_t a4base = sb + (uint32_t)(((wn + 8 * (mi >> 1) + q) * WSTRIDE
                                             + 8 * (mi & 1)) * 2);
    const uint32_t a2base = sb + (uint32_t)(((wn + 16 + q) * WSTRIDE
                                             + 8 * (mi & 1)) * 2);

#define CMPK(AH, AL, KB, ACC) {                                               \
    unsigned h0r,h1r,h2r,h3r,h4r,h5r,l0r,l1r,l2r,l3r,l4r,l5r;                 \
    ldsm4(a4base + (KB), h0r, h1r, h2r, h3r);                                 \
    ldsm2(a2base + (KB), h4r, h5r);                                           \
    ldsm4(a4base + WLO + (KB), l0r, l1r, l2r, l3r);                           \
    ldsm2(a2base + WLO + (KB), l4r, l5r);                                     \
    mma4(ACC[0], (AH).x,(AH).y,(AH).z,(AH).w, h0r, h1r);                      \
    mma4(ACC[1], (AH).x,(AH).y,(AH).z,(AH).w, h2r, h3r);                      \
    mma4(ACC[2], (AH).x,(AH).y,(AH).z,(AH).w, h4r, h5r);                      \
    mma4(ACC[0], (AH).x,(AH).y,(AH).z,(AH).w, l0r, l1r);                      \
    mma4(ACC[1], (AH).x,(AH).y,(AH).z,(AH).w, l2r, l3r);                      \
    mma4(ACC[2], (AH).x,(AH).y,(AH).z,(AH).w, l4r, l5r);                      \
    mma4(ACC[0], (AL).x,(AL).y,(AL).z,(AL).w, h0r, h1r);                      \
    mma4(ACC[1], (AL).x,(AL).y,(AL).z,(AL).w, h2r, h3r);                      \
    mma4(ACC[2], (AL).x,(AL).y,(AL).z,(AL).w, h4r, h5r); }

    float* xpc = g_xp + (size_t)blockIdx.x * TT * (32 * 48);

    // ================= PHASE 1: x_proj for all t (throughput) =============
    {
        const int mt = grp * 2 + (w & 1);
        for (int t = kw; t < TT; t += 2) {
            const uint4* xb = (const uint4*)g_xf
                              + ((size_t)mt * TT + t) * (16 * 64) + lane;
            float acc[3][4] = {{0,0,0,0},{0,0,0,0},{0,0,0,0}};
            #pragma unroll
            for (int ks = 0; ks < 16; ks++) {
                uint4 AH = xb[ks * 64];
                uint4 AL = xb[ks * 64 + 32];
                CMPK(AH, AL, (uint32_t)(ks * 32), acc);
            }
            float* xpt = xpc + (size_t)t * (32 * 48);
            #pragma unroll
            for (int nf = 0; nf < 3; nf++) {
                int n0 = wn + nf * 8 + (lane & 3) * 2;
                int r0 = wm + (lane >> 2);
                *(float2*)(xpt + r0 * 48 + n0)       = make_float2(acc[nf][0], acc[nf][1]);
                *(float2*)(xpt + (r0 + 8) * 48 + n0) = make_float2(acc[nf][2], acc[nf][3]);
            }
        }
    }
    __syncthreads();

    // ================= PHASE 2: latency-critical scan =====================
    const int mg  = (tid >> 4) * 2;
    const int jlg = tid & 15;
    float hprev[2];
    hprev[0] = h0[(bm0 + mg) * HHID + j0 + jlg];
    hprev[1] = h0[(bm0 + mg + 1) * HHID + j0 + jlg];

    const uint32_t HKB = (uint32_t)((II + kw * 256) * 2);
    const int mt2 = (bm0 >> 4) + (wm >> 4);   // this warp's A m-tile

    for (int t = 0; t < TT; t++) {
        const int pr = (t + 1) & 1;
        const int pw = t & 1;

        // -- A-frags straight from global (coalesced LDG.128, pipelined) --
        const uint4* hfb = g_hf[pr] + ((size_t)mt2 * 32 + kw * 16) * 64 + lane;
        uint4 bufH[4], bufL[4];
        #pragma unroll
        for (int p = 0; p < 4; p++) {
            bufH[p] = hfb[p * 64];
            bufL[p] = hfb[p * 64 + 32];
        }

        // -- x_proj gate operands (independent; issue early) --
        const float* xpt = xpc + (size_t)t * (32 * 48);
        float xg[2][3];
        #pragma unroll
        for (int i = 0; i < 2; i++) {
            xg[i][0] = xpt[(mg + i) * 48 + jlg];
            xg[i][1] = xpt[(mg + i) * 48 + 16 + jlg];
            xg[i][2] = xpt[(mg + i) * 48 + 32 + jlg];
        }

        float accA[3][4] = {{0,0,0,0},{0,0,0,0},{0,0,0,0}};
        float accB[3][4] = {{0,0,0,0},{0,0,0,0},{0,0,0,0}};
        #pragma unroll
        for (int ks = 0; ks < 16; ks++) {
            uint4 AH = bufH[ks & 3];
            uint4 AL = bufL[ks & 3];
            if (ks + 4 < 16) {
                bufH[ks & 3] = hfb[(ks + 4) * 64];
                bufL[ks & 3] = hfb[(ks + 4) * 64 + 32];
            }
            if (ks & 1) { CMPK(AH, AL, HKB + (uint32_t)(ks * 32), accB); }
            else        { CMPK(AH, AL, HKB + (uint32_t)(ks * 32), accA); }
        }
        {
            float* scr = kw ? scrH1 : scrH0;
            #pragma unroll
            for (int nf = 0; nf < 3; nf++) {
                int n0 = wn + nf * 8 + (lane & 3) * 2;
                int r0 = wm + (lane >> 2);
                scr[n0 * 33 + r0]           = accA[nf][0] + accB[nf][0];
                scr[(n0 + 1) * 33 + r0]     = accA[nf][1] + accB[nf][1];
                scr[n0 * 33 + r0 + 8]       = accA[nf][2] + accB[nf][2];
                scr[(n0 + 1) * 33 + r0 + 8] = accA[nf][3] + accB[nf][3];
            }
        }
        __syncthreads();

        // -- gates: thread owns (b = bm0+mg+i, j = j0+jlg) --
        #pragma unroll
        for (int i = 0; i < 2; i++) {
            int m = mg + i;
            float hr = scrH0[jlg * 33 + m]        + scrH1[jlg * 33 + m];
            float hz = scrH0[(16 + jlg) * 33 + m] + scrH1[(16 + jlg) * 33 + m];
            float hh = scrH0[(32 + jlg) * 33 + m] + scrH1[(32 + jlg) * 33 + m];
            float r  = 1.f / (1.f + __expf(-(xg[i][0] + hr + bias[jlg])));
            float z  = 1.f / (1.f + __expf(-(xg[i][1] + hz + bias[16 + jlg])));
            float n  = tanhf(xg[i][2] + bias[32 + jlg] + r * (hh + bias[48 + jlg]));
            float hn = (1.f - z) * n + z * hprev[i];
            hprev[i] = hn;
            scrF[jlg * 33 + m] = hn;
            if (t == TT - 1) {
                int o = (bm0 + m) * 2048 + j0 + jlg;
                out[o]                 = r;  out[o + 262144]        = r;
                out[o + 512]           = z;  out[o + 512 + 262144]  = z;
                out[o + 1024]          = n;  out[o + 1024 + 262144] = n;
                out[o + 1536]          = hn; out[o + 1536 + 262144] = hn;
            }
        }
        __syncthreads();

        // -- build new-h fragments, coalesced STG.128 --
        if (tid < 64) {
            int mtL = tid >> 5, ln = tid & 31;
            int rl2 = ln >> 2, c2b = (ln & 3) * 2;
            int rb  = mtL * 16 + rl2;
            unsigned fh0,fl0,fh1,fl1,fh2,fl2,fh3,fl3;
            cvt_hilo(make_float2(scrF[c2b * 33 + rb],       scrF[(c2b + 1) * 33 + rb]),     fh0, fl0);
            cvt_hilo(make_float2(scrF[c2b * 33 + rb + 8],   scrF[(c2b + 1) * 33 + rb + 8]), fh1, fl1);
            cvt_hilo(make_float2(scrF[(c2b + 8) * 33 + rb],     scrF[(c2b + 9) * 33 + rb]),     fh2, fl2);
            cvt_hilo(make_float2(scrF[(c2b + 8) * 33 + rb + 8], scrF[(c2b + 9) * 33 + rb + 8]), fh3, fl3);
            size_t base = ((size_t)((bm0 >> 4) + mtL) * 32 + kcP) * 64;
            g_hf[pw][base + ln]      = make_uint4(fh0, fh1, fh2, fh3);
            g_hf[pw][base + 32 + ln] = make_uint4(fl0, fl1, fl2, fl3);
        }

        // -- group barrier (32 CTAs sharing this batch group) --
        if (t < TT - 1) {
            __threadfence();
            __syncthreads();
            if (tid == 0) {
                int old = atomicAdd(&g_count4[grp * 32], 1);
                if (old == GROUPN - 1) {
                    g_count4[grp * 32] = 0;
                    __threadfence();
                    g_flag4[grp * 32] = t + 1;
                } else {
                    while (g_flag4[grp * 32] < t + 1) { }
                    __threadfence();
                }
            }
            __syncthreads();
        }
    }

    // reset barrier state for next graph replay
    __syncthreads();
    if (tid == 0) {
        int old = atomicAdd(&g_count4[grp * 32], 1);
        if (old == GROUPN - 1) {
            g_count4[grp * 32] = 0;
            g_flag4[grp * 32] = 0;
            __threadfence();
        }
    }
}

extern "C" void kernel_launch(void* const* d_in, const int* in_sizes, int n_in,
                              void* d_out, int out_size) {
    const float* x   = (const float*)d_in[0];
    const float* h   = (const float*)d_in[1];
    const float* Wih = (const float*)d_in[2];
    const float* bih = (const float*)d_in[3];
    const float* Whh = (const float*)d_in[4];
    const float* bhh = (const float*)d_in[5];
    float* out = (float*)d_out;

    prep_kernel<<<8192, 256>>>(x, h);

    cudaFuncSetAttribute(gru_mma, cudaFuncAttributeMaxDynamicSharedMemorySize,
                         SMEM_BYTES);
    gru_mma<<<GRID, NTHREADS, SMEM_BYTES>>>(h, Wih, bih, Whh, bhh, out);
}